// round 1
// baseline (speedup 1.0000x reference)
#include <cuda_runtime.h>

#define ZS   512
#define MM   512
#define HHN  511
#define NB   65536

// ---------------- scratch (static device globals; no allocation) ----------------
__device__ float g_vn[HHN * ZS];              // normalized Householder vectors
__device__ float g_q [ZS * MM];               // q = prod(I - 2 v v^T)
__device__ float g_A [ZS * MM];               // A  = q @ r1
__device__ float g_Bt[ZS * MM];               // Bt = q @ r2^T
__device__ float g_rrii[MM];                  // diag(r1)*diag(r2)
__device__ float g_hB[(size_t)NB * MM];       // tanh(z@Bt + c)

typedef unsigned long long u64;

__device__ __forceinline__ u64 fma2(u64 a, u64 b, u64 c) {
    u64 d;
    asm("fma.rn.f32x2 %0, %1, %2, %3;" : "=l"(d) : "l"(a), "l"(b), "l"(c));
    return d;
}
__device__ __forceinline__ void unpack2(u64 p, float& lo, float& hi) {
    asm("mov.b64 {%0, %1}, %2;" : "=f"(lo), "=f"(hi) : "l"(p));
}

// ---------------- init: rrii + zero ldj ----------------
__global__ void init_kernel(const float* __restrict__ Rs,
                            const float* __restrict__ r2diag,
                            float* __restrict__ ldj) {
    int i = blockIdx.x * blockDim.x + threadIdx.x;
    if (i < MM) g_rrii[i] = Rs[(size_t)i * MM + i] * r2diag[i];
    if (i < NB) ldj[i] = 0.f;
}

// ---------------- normalize v rows ----------------
__global__ void normalize_kernel(const float* __restrict__ v) {
    int row = blockIdx.x;           // 0..510
    int tid = threadIdx.x;          // 256 threads
    float a = v[row * ZS + tid];
    float b = v[row * ZS + tid + 256];
    float s = a * a + b * b;
    #pragma unroll
    for (int o = 16; o > 0; o >>= 1) s += __shfl_xor_sync(0xffffffffu, s, o);
    __shared__ float ws[8];
    if ((tid & 31) == 0) ws[tid >> 5] = s;
    __syncthreads();
    float tot = ws[0] + ws[1] + ws[2] + ws[3] + ws[4] + ws[5] + ws[6] + ws[7];
    float inv = rsqrtf(tot);
    g_vn[row * ZS + tid]       = a * inv;
    g_vn[row * ZS + tid + 256] = b * inv;
}

// ---------------- Householder scan: one warp per row of q ----------------
__global__ void __launch_bounds__(256) scan_kernel() {
    __shared__ float sv[2][ZS];
    int tid  = threadIdx.x;
    int lane = tid & 31, warp = tid >> 5;
    int row  = blockIdx.x * 8 + warp;       // 64 blocks * 8 warps = 512 rows
    int base = lane * 16;                   // 16 contiguous cols per lane

    float f[16];
    #pragma unroll
    for (int j = 0; j < 16; j++) f[j] = (base + j == row) ? 1.f : 0.f;

    { // preload v_0
        float2 t = *(const float2*)&g_vn[tid * 2];
        sv[0][tid * 2] = t.x; sv[0][tid * 2 + 1] = t.y;
    }
    __syncthreads();

    for (int i = 0; i < HHN; i++) {
        float2 nx;
        bool pf = (i + 1 < HHN);
        if (pf) nx = *(const float2*)&g_vn[(size_t)(i + 1) * ZS + tid * 2];

        const float*  cv  = sv[i & 1];
        const float4* cv4 = (const float4*)(cv + base);
        float vv[16];
        #pragma unroll
        for (int j4 = 0; j4 < 4; j4++) {
            float4 V = cv4[j4];
            vv[j4*4+0] = V.x; vv[j4*4+1] = V.y; vv[j4*4+2] = V.z; vv[j4*4+3] = V.w;
        }
        float d0 = 0, d1 = 0, d2 = 0, d3 = 0;
        #pragma unroll
        for (int j4 = 0; j4 < 4; j4++) {
            d0 = fmaf(f[j4*4+0], vv[j4*4+0], d0);
            d1 = fmaf(f[j4*4+1], vv[j4*4+1], d1);
            d2 = fmaf(f[j4*4+2], vv[j4*4+2], d2);
            d3 = fmaf(f[j4*4+3], vv[j4*4+3], d3);
        }
        float dot = (d0 + d1) + (d2 + d3);
        #pragma unroll
        for (int o = 16; o > 0; o >>= 1) dot += __shfl_xor_sync(0xffffffffu, dot, o);
        dot *= 2.f;
        #pragma unroll
        for (int j = 0; j < 16; j++) f[j] = fmaf(-dot, vv[j], f[j]);

        if (pf) {
            float* nb = sv[(i + 1) & 1];
            nb[tid * 2] = nx.x; nb[tid * 2 + 1] = nx.y;
        }
        __syncthreads();
    }

    float4* qo = (float4*)&g_q[(size_t)row * ZS + base];
    qo[0] = make_float4(f[0],  f[1],  f[2],  f[3]);
    qo[1] = make_float4(f[4],  f[5],  f[6],  f[7]);
    qo[2] = make_float4(f[8],  f[9],  f[10], f[11]);
    qo[3] = make_float4(f[12], f[13], f[14], f[15]);
}

// ---------------- small GEMMs: A = q@r1 (mode 0), Bt = q@r2^T (mode 1) ----------------
__global__ void __launch_bounds__(256) small_gemm_kernel(const float* __restrict__ Rs,
                                                         const float* __restrict__ r2diag) {
    __shared__ float Qs[16][68];
    __shared__ float Bs[16][68];
    int tid = threadIdx.x;
    int tx = tid & 15, ty = tid >> 4;
    int j0 = blockIdx.x * 64, i0 = blockIdx.y * 64;
    int mode = blockIdx.z;
    float acc[4][4] = {};

    for (int kt = 0; kt < 32; kt++) {
        { // Q tile 64(i) x 16(k), transposed into Qs[k][i]
            int i = tid >> 2, kq = tid & 3;
            float4 qv = *(const float4*)&g_q[(size_t)(i0 + i) * ZS + kt * 16 + kq * 4];
            Qs[kq*4+0][i] = qv.x; Qs[kq*4+1][i] = qv.y;
            Qs[kq*4+2][i] = qv.z; Qs[kq*4+3][i] = qv.w;
        }
        { // B tile 16(k) x 64(j), built on the fly
            int kr = tid >> 4, nq = tid & 15;
            int kg = kt * 16 + kr;
            int jg0 = j0 + nq * 4;
            if (mode == 0) {  // r1[k,j] = (k<=j) ? Rs[k,j] : 0
                float4 bv = *(const float4*)&Rs[(size_t)kg * MM + jg0];
                Bs[kr][nq*4+0] = (kg <= jg0 + 0) ? bv.x : 0.f;
                Bs[kr][nq*4+1] = (kg <= jg0 + 1) ? bv.y : 0.f;
                Bs[kr][nq*4+2] = (kg <= jg0 + 2) ? bv.z : 0.f;
                Bs[kr][nq*4+3] = (kg <= jg0 + 3) ? bv.w : 0.f;
            } else {          // r2^T[k,j] = r2[j,k] = (k>j)?Rs[j,k] : (k==j)?r2diag[j] : 0
                #pragma unroll
                for (int e = 0; e < 4; e++) {
                    int jg = jg0 + e;
                    float val;
                    if      (kg >  jg) val = Rs[(size_t)jg * MM + kg];
                    else if (kg == jg) val = r2diag[jg];
                    else               val = 0.f;
                    Bs[kr][nq*4+e] = val;
                }
            }
        }
        __syncthreads();
        #pragma unroll
        for (int kk = 0; kk < 16; kk++) {
            float a[4], b[4];
            #pragma unroll
            for (int e = 0; e < 4; e++) { a[e] = Qs[kk][ty*4+e]; b[e] = Bs[kk][tx*4+e]; }
            #pragma unroll
            for (int x = 0; x < 4; x++)
                #pragma unroll
                for (int y = 0; y < 4; y++)
                    acc[x][y] = fmaf(a[x], b[y], acc[x][y]);
        }
        __syncthreads();
    }
    float* outp = (mode == 0) ? g_A : g_Bt;
    #pragma unroll
    for (int x = 0; x < 4; x++)
        #pragma unroll
        for (int y = 0; y < 4; y++)
            outp[(size_t)(i0 + ty*4 + x) * MM + j0 + tx*4 + y] = acc[x][y];
}

// ---------------- big GEMM 1: hB = tanh(z @ Bt + c), ldj partials ----------------
// 128x128x16 tiles, 256 threads, 8x8 microtile via fma.rn.f32x2.
// Thread (tx,ty): rows m0+ty*8+i, col pairs n0 + 32*jp + 2*tx (+0/1).
__global__ void __launch_bounds__(256, 2) gemm1_kernel(const float* __restrict__ z,
                                                       const float* __restrict__ c,
                                                       float* __restrict__ ldj) {
    __shared__ float As2[16][260];   // A values duplicated: As2[k][2m]=As2[k][2m+1]
    __shared__ float Bs [16][132];
    int tid = threadIdx.x;
    int tx = tid & 15, ty = tid >> 4;
    int n0 = blockIdx.x * 128;
    int m0 = blockIdx.y * 128;
    u64 acc[8][4];
    #pragma unroll
    for (int i = 0; i < 8; i++)
        #pragma unroll
        for (int jp = 0; jp < 4; jp++) acc[i][jp] = 0ull;

    for (int kt = 0; kt < 32; kt++) {
        #pragma unroll
        for (int l = 0; l < 2; l++) {     // A tile = z, duplicated stores
            int idx = tid + l * 256;
            int m = idx >> 2, kq = idx & 3;
            float4 av = *(const float4*)&z[(size_t)(m0 + m) * ZS + kt * 16 + kq * 4];
            *(float2*)&As2[kq*4+0][2*m] = make_float2(av.x, av.x);
            *(float2*)&As2[kq*4+1][2*m] = make_float2(av.y, av.y);
            *(float2*)&As2[kq*4+2][2*m] = make_float2(av.z, av.z);
            *(float2*)&As2[kq*4+3][2*m] = make_float2(av.w, av.w);
        }
        #pragma unroll
        for (int l = 0; l < 2; l++) {     // B tile = Bt rows
            int idx = tid + l * 256;
            int kr = idx >> 5, nq = idx & 31;
            float4 bv = *(const float4*)&g_Bt[(size_t)(kt * 16 + kr) * MM + n0 + nq * 4];
            *(float4*)&Bs[kr][nq * 4] = bv;
        }
        __syncthreads();
        #pragma unroll
        for (int kk = 0; kk < 16; kk++) {
            u64 a[8], b[4];
            #pragma unroll
            for (int i = 0; i < 8; i++)  a[i]  = *(const u64*)&As2[kk][2 * (ty * 8 + i)];
            #pragma unroll
            for (int jp = 0; jp < 4; jp++) b[jp] = *(const u64*)&Bs[kk][32 * jp + 2 * tx];
            #pragma unroll
            for (int i = 0; i < 8; i++)
                #pragma unroll
                for (int jp = 0; jp < 4; jp++)
                    acc[i][jp] = fma2(a[i], b[jp], acc[i][jp]);
        }
        __syncthreads();
    }

    float cc[8], rr[8];
    #pragma unroll
    for (int jp = 0; jp < 4; jp++) {
        int col = n0 + 32 * jp + 2 * tx;
        cc[2*jp] = c[col];       cc[2*jp+1] = c[col + 1];
        rr[2*jp] = g_rrii[col];  rr[2*jp+1] = g_rrii[col + 1];
    }
    #pragma unroll
    for (int i = 0; i < 8; i++) {
        int row = m0 + ty * 8 + i;
        float s = 0.f;
        #pragma unroll
        for (int jp = 0; jp < 4; jp++) {
            float v0, v1; unpack2(acc[i][jp], v0, v1);
            int col = n0 + 32 * jp + 2 * tx;
            float h0 = tanhf(v0 + cc[2*jp]);
            float h1 = tanhf(v1 + cc[2*jp+1]);
            *(float2*)&g_hB[(size_t)row * MM + col] = make_float2(h0, h1);
            float d0 = 1.f - h0 * h0;
            float d1 = 1.f - h1 * h1;
            s += __logf(fabsf(fmaf(d0, rr[2*jp],   1.f)));
            s += __logf(fabsf(fmaf(d1, rr[2*jp+1], 1.f)));
        }
        s += __shfl_xor_sync(0xffffffffu, s, 8);
        s += __shfl_xor_sync(0xffffffffu, s, 4);
        s += __shfl_xor_sync(0xffffffffu, s, 2);
        s += __shfl_xor_sync(0xffffffffu, s, 1);
        if (tx == 0) atomicAdd(&ldj[row], s);
    }
}

// ---------------- big GEMM 2: z_out = hB @ A^T + z ----------------
__global__ void __launch_bounds__(256, 2) gemm2_kernel(const float* __restrict__ z,
                                                       float* __restrict__ out) {
    __shared__ float As2[16][260];
    __shared__ float Bs [16][132];
    int tid = threadIdx.x;
    int tx = tid & 15, ty = tid >> 4;
    int n0 = blockIdx.x * 128;
    int m0 = blockIdx.y * 128;
    u64 acc[8][4];
    #pragma unroll
    for (int i = 0; i < 8; i++)
        #pragma unroll
        for (int jp = 0; jp < 4; jp++) acc[i][jp] = 0ull;

    for (int kt = 0; kt < 32; kt++) {
        #pragma unroll
        for (int l = 0; l < 2; l++) {     // A tile = hB, duplicated
            int idx = tid + l * 256;
            int m = idx >> 2, kq = idx & 3;
            float4 av = *(const float4*)&g_hB[(size_t)(m0 + m) * MM + kt * 16 + kq * 4];
            *(float2*)&As2[kq*4+0][2*m] = make_float2(av.x, av.x);
            *(float2*)&As2[kq*4+1][2*m] = make_float2(av.y, av.y);
            *(float2*)&As2[kq*4+2][2*m] = make_float2(av.z, av.z);
            *(float2*)&As2[kq*4+3][2*m] = make_float2(av.w, av.w);
        }
        #pragma unroll
        for (int l = 0; l < 2; l++) {     // B tile: B[mk][n] = g_A[n0+n][mk] (transposed)
            int idx = tid + l * 256;
            int n = idx >> 2, q = idx & 3;
            float4 t = *(const float4*)&g_A[(size_t)(n0 + n) * MM + kt * 16 + q * 4];
            Bs[q*4+0][n] = t.x; Bs[q*4+1][n] = t.y;
            Bs[q*4+2][n] = t.z; Bs[q*4+3][n] = t.w;
        }
        __syncthreads();
        #pragma unroll
        for (int kk = 0; kk < 16; kk++) {
            u64 a[8], b[4];
            #pragma unroll
            for (int i = 0; i < 8; i++)  a[i]  = *(const u64*)&As2[kk][2 * (ty * 8 + i)];
            #pragma unroll
            for (int jp = 0; jp < 4; jp++) b[jp] = *(const u64*)&Bs[kk][32 * jp + 2 * tx];
            #pragma unroll
            for (int i = 0; i < 8; i++)
                #pragma unroll
                for (int jp = 0; jp < 4; jp++)
                    acc[i][jp] = fma2(a[i], b[jp], acc[i][jp]);
        }
        __syncthreads();
    }

    #pragma unroll
    for (int i = 0; i < 8; i++) {
        int row = m0 + ty * 8 + i;
        #pragma unroll
        for (int jp = 0; jp < 4; jp++) {
            float v0, v1; unpack2(acc[i][jp], v0, v1);
            int col = n0 + 32 * jp + 2 * tx;
            float2 zp = *(const float2*)&z[(size_t)row * ZS + col];
            *(float2*)&out[(size_t)row * ZS + col] = make_float2(v0 + zp.x, v1 + zp.y);
        }
    }
}

// ---------------- launch ----------------
extern "C" void kernel_launch(void* const* d_in, const int* in_sizes, int n_in,
                              void* d_out, int out_size) {
    const float* z      = (const float*)d_in[0];
    const float* v      = (const float*)d_in[1];
    const float* Rs     = (const float*)d_in[2];
    const float* r2diag = (const float*)d_in[3];
    const float* c      = (const float*)d_in[4];
    float* out = (float*)d_out;
    float* ldj = out + (size_t)NB * ZS;   // output layout: [z_out (65536x512), ldj (65536)]

    init_kernel<<<NB / 256, 256>>>(Rs, r2diag, ldj);
    normalize_kernel<<<HHN, 256>>>(v);
    scan_kernel<<<64, 256>>>();
    small_gemm_kernel<<<dim3(8, 8, 2), 256>>>(Rs, r2diag);
    gemm1_kernel<<<dim3(4, 512), 256>>>(z, c, ldj);
    gemm2_kernel<<<dim3(4, 512), 256>>>(z, out);
}